// round 17
// baseline (speedup 1.0000x reference)
#include <cuda_runtime.h>

// FoldLayer fold (col2im), K=3, S=2, D=1, pad=1, cropped.
// patches: (B=16, GH=64, GW=64, 9*128) fp32, slot-major (i*3+j)*128+c
// out:     (B=16, 128, 128, 128) fp32
//
// Pair-quad gather, persistent grid-stride: 444 blocks (148 SM x 3 resident),
// each looping over 2x4 output tiles. Per tile (one warp):
//   out(2Y,  2X)   = P(Y,X)[s4]
//   out(2Y,  2X+1) = P(Y,X)[s5] + P(Y,X+1)[s3]
//   out(2Y+1,2X)   = P(Y,X)[s7] + P(Y+1,X)[s1]
//   out(2Y+1,2X+1) = P(Y,X)[s8] + P(Y,X+1)[s6] + P(Y+1,X)[s2] + P(Y+1,X+1)[s0]
// 18 independent LDG.128 per tile; grid-stride removes per-wave CTA relaunch
// and cold-start stalls (9.2 waves -> 1 persistent wave). Stores are
// fire-and-forget so successive iterations' load batches issue back-to-back.

#define GH_  64
#define GW_  64
#define C4_  32              // 128 floats = 32 float4 per lane
#define PSTRIDE (9 * C4_)    // float4s per patch = 288
#define ROWSTRIDE (GW_ * PSTRIDE)
#define NTILES (16 * 64 * 32)    // 32768 warp-tiles
#define NBLOCKS 444              // 148 SMs x 3 resident blocks
#define TILES_PER_BLOCK_STEP (NBLOCKS * 8)   // tiles consumed per grid-stride step

__device__ __forceinline__ void acc4(float4& a, const float4 v) {
    a.x += v.x; a.y += v.y; a.z += v.z; a.w += v.w;
}

__global__ __launch_bounds__(256, 3)
void fold_pair_persist(const float4* __restrict__ p, float4* __restrict__ out) {
    const int lane  = threadIdx.x & 31;
    const int wslot = threadIdx.x >> 5;                 // 0..7
    const float4 z = make_float4(0.f, 0.f, 0.f, 0.f);

    #pragma unroll 1
    for (int tile = blockIdx.x * 8 + wslot; tile < NTILES; tile += TILES_PER_BLOCK_STEP) {
        // tile -> (b, Y, Xp)
        const int Xp = tile & 31;
        const int Y  = (tile >> 5) & 63;
        const int b  = tile >> 11;
        const int X0 = Xp << 1;                         // 0..62, even

        const bool okY  = (Y < 63);
        const bool okX1 = (X0 < 62);

        const int pbA = ((b * GH_ + Y) * GW_ + X0) * PSTRIDE + lane;  // (Y,X0)
        const int pbB = pbA + PSTRIDE;                                // (Y,X0+1)
        const int pcA = pbA + ROWSTRIDE;                              // (Y+1,X0)
        const int pcB = pcA + PSTRIDE;                                // (Y+1,X0+1)

        // 10 unconditional loads front-batched
        const float4 A4 = __ldg(&p[pbA + 4 * C4_]);
        const float4 A5 = __ldg(&p[pbA + 5 * C4_]);
        const float4 A7 = __ldg(&p[pbA + 7 * C4_]);
        const float4 A8 = __ldg(&p[pbA + 8 * C4_]);
        const float4 A3 = __ldg(&p[pbB + 3 * C4_]);
        const float4 A6 = __ldg(&p[pbB + 6 * C4_]);
        const float4 B4 = __ldg(&p[pbB + 4 * C4_]);
        const float4 B5 = __ldg(&p[pbB + 5 * C4_]);
        const float4 B7 = __ldg(&p[pbB + 7 * C4_]);
        const float4 B8 = __ldg(&p[pbB + 8 * C4_]);

        // 8 predicated edge loads (warp-uniform predicates)
        const float4 A1 = okY ? __ldg(&p[pcA + 1 * C4_]) : z;
        const float4 A2 = okY ? __ldg(&p[pcA + 2 * C4_]) : z;
        const float4 A0 = okY ? __ldg(&p[pcB + 0 * C4_]) : z;
        const float4 B1 = okY ? __ldg(&p[pcB + 1 * C4_]) : z;
        const float4 B2 = okY ? __ldg(&p[pcB + 2 * C4_]) : z;
        const float4 B3 = okX1 ? __ldg(&p[pbB + PSTRIDE + 3 * C4_]) : z;
        const float4 B6 = okX1 ? __ldg(&p[pbB + PSTRIDE + 6 * C4_]) : z;
        const float4 B0 = (okY && okX1) ? __ldg(&p[pcB + PSTRIDE + 0 * C4_]) : z;

        // accumulate
        float4 a00 = A4;
        float4 a01 = A5;  acc4(a01, A3);
        float4 a10 = A7;  acc4(a10, A1);
        float4 a11 = A8;  acc4(a11, A6);  acc4(a11, A2);  acc4(a11, A0);

        float4 b00 = B4;
        float4 b01 = B5;  acc4(b01, B3);
        float4 b10 = B7;  acc4(b10, B1);
        float4 b11 = B8;  acc4(b11, B6);  acc4(b11, B2);  acc4(b11, B0);

        // stores: two 2KB-contiguous runs
        const int ob = ((b * 128 + 2 * Y) * 128 + 2 * X0) * C4_ + lane;
        out[ob]            = a00;
        out[ob + 1 * C4_]  = a01;
        out[ob + 2 * C4_]  = b00;
        out[ob + 3 * C4_]  = b01;
        const int ob2 = ob + 128 * C4_;
        out[ob2]           = a10;
        out[ob2 + 1 * C4_] = a11;
        out[ob2 + 2 * C4_] = b10;
        out[ob2 + 3 * C4_] = b11;
    }
}

extern "C" void kernel_launch(void* const* d_in, const int* in_sizes, int n_in,
                              void* d_out, int out_size) {
    (void)in_sizes; (void)n_in; (void)out_size;
    const float4* p = (const float4*)d_in[0];
    float4* out = (float4*)d_out;

    fold_pair_persist<<<NBLOCKS, 256>>>(p, out);
}